// round 7
// baseline (speedup 1.0000x reference)
#include <cuda_runtime.h>
#include <cstdint>

// AttentionDownsampler v7: two streaming kernels; K3 now channel-looped so
// per-CTA setup (attn pull, coef regs, barriers) amortizes over 48 channels.
//  K1: pixel_dot = sum_c hr*aw (half-slab CTAs, 2-acc c-loop) + softmax -> g_attn.
//  K3: CTA = (slab, 48-channel group); attn coefs are channel-invariant
//      registers; loop 3 x (7 LDG.128 + FMA + smem-atomic combine).

#define DIM     384
#define KS      7
#define NP      49
#define HW      112
#define PLANE   (HW * HW)
#define FN      16
#define NSLAB   128               // (b, ph)
#define SLABPIX 784
#define DROP_P  0.2f

#define CPGO    48                // channels per K3 CTA
#define NCG2    8                 // 384 / 48
#define T3      448               // (x4:28, cc:16)

__device__ float g_attn[(size_t)NSLAB * SLABPIX];   // [slab][pw][49]

// ================= K1: pixel dot + softmax (half-slab CTAs) ==============
__global__ void __launch_bounds__(392, 2)
k1_dot_softmax(const float* __restrict__ hr,
               const float* __restrict__ du,
               const float* __restrict__ aw,
               const float* __restrict__ ab,
               const float* __restrict__ wmat,
               const float* __restrict__ bmat)
{
    __shared__ float awsh[DIM];
    __shared__ float pd_s[392];

    const int bid  = blockIdx.x;
    const int xh   = bid & 1;            // x half: columns [xh*56, xh*56+56)
    const int slab = bid >> 1;
    const int ph   = slab & (FN - 1);
    const int b    = slab >> 4;

    const int tid = threadIdx.x;         // tid = dy*56 + xl
    const int dy  = tid / 56;
    const int xl  = tid - dy * 56;

    if (tid < DIM) awsh[tid] = __ldg(aw + tid);
    __syncthreads();

    const float* gp = hr + (size_t)b * DIM * PLANE
                         + (size_t)(ph * KS + dy) * HW + xh * 56 + xl;

    float s0 = 0.f, s1 = 0.f;
    #pragma unroll 8
    for (int c = 0; c < DIM; c += 2) {
        s0 = fmaf(__ldg(gp + (size_t)c * PLANE),       awsh[c],     s0);
        s1 = fmaf(__ldg(gp + (size_t)(c + 1) * PLANE), awsh[c + 1], s1);
    }
    pd_s[tid] = s0 + s1;
    __syncthreads();

    // softmax: warp w (0..7) handles patch pw = xh*8 + w
    const int wid = tid >> 5, lane = tid & 31;
    if (wid < 8) {
        const int pw = xh * 8 + wid;
        const float m   = (__ldg(du + (b * FN + ph) * FN + pw) > DROP_P) ? 1.f : 0.f;
        const float abv = __ldg(ab);
        const int p0 = lane, p1 = lane + 32;
        float v0 = -1e30f, v1 = -1e30f;
        if (p0 < NP) {
            int d = p0 / KS, e = p0 - d * KS;
            v0 = (pd_s[d * 56 + wid * KS + e] + abv) * m * __ldg(wmat + p0) + __ldg(bmat + p0);
        }
        if (p1 < NP) {
            int d = p1 / KS, e = p1 - d * KS;
            v1 = (pd_s[d * 56 + wid * KS + e] + abv) * m * __ldg(wmat + p1) + __ldg(bmat + p1);
        }
        float mx = fmaxf(v0, v1);
        #pragma unroll
        for (int o = 16; o; o >>= 1)
            mx = fmaxf(mx, __shfl_xor_sync(0xffffffffu, mx, o));
        float e0 = (p0 < NP) ? __expf(v0 - mx) : 0.f;
        float e1 = (p1 < NP) ? __expf(v1 - mx) : 0.f;
        float ss = e0 + e1;
        #pragma unroll
        for (int o = 16; o; o >>= 1)
            ss += __shfl_xor_sync(0xffffffffu, ss, o);
        const float inv = 1.f / ss;
        float* dst = g_attn + (size_t)slab * SLABPIX + pw * NP;
        if (p0 < NP) dst[p0] = e0 * inv;
        if (p1 < NP) dst[p1] = e1 * inv;
    }
}

// ================= K3: channel-looped register epilogue ==================
__global__ void __launch_bounds__(T3, 4)
k3_epilogue(const float* __restrict__ hr, float* __restrict__ out)
{
    __shared__ float attn_s[SLABPIX];
    __shared__ float out_s[CPGO * FN];   // [48ch][16pw] = 3 KB

    const int bid   = blockIdx.x;
    const int slab  = bid / NCG2;
    const int cg    = bid - slab * NCG2;
    const int ph    = slab & (FN - 1);
    const int b     = slab >> 4;
    const int cbase = cg * CPGO;

    const int tid = threadIdx.x;
    const int x4  = tid % 28;            // float4 column
    const int cc  = tid / 28;            // channel phase 0..15

    for (int i = tid; i < SLABPIX; i += T3)
        attn_s[i] = __ldg(g_attn + (size_t)slab * SLABPIX + i);
    for (int i = tid; i < CPGO * FN; i += T3)
        out_s[i] = 0.f;
    __syncthreads();

    // channel-invariant attn coefficients for this thread's 4 x-positions
    int pwk[4];
    float coef[4][KS];
    #pragma unroll
    for (int k = 0; k < 4; k++) {
        const int x  = 4 * x4 + k;
        const int pw = x / KS;
        pwk[k] = pw;
        const int ci = pw * NP + (x - pw * KS);
        #pragma unroll
        for (int d = 0; d < KS; d++)
            coef[k][d] = attn_s[ci + d * KS];
    }

    const float* base = hr + (size_t)(b * DIM + cbase + cc) * PLANE
                           + (size_t)(ph * KS) * HW;

    #pragma unroll
    for (int g = 0; g < 3; g++) {
        const float4* gp = (const float4*)(base + (size_t)(g * 16) * PLANE) + x4;
        float acc[4] = {0.f, 0.f, 0.f, 0.f};
        #pragma unroll
        for (int d = 0; d < KS; d++) {
            float4 v = __ldg(gp + d * 28);
            acc[0] = fmaf(v.x, coef[0][d], acc[0]);
            acc[1] = fmaf(v.y, coef[1][d], acc[1]);
            acc[2] = fmaf(v.z, coef[2][d], acc[2]);
            acc[3] = fmaf(v.w, coef[3][d], acc[3]);
        }
        // combine the <=2 distinct pw groups into smem
        float* orow = out_s + (g * 16 + cc) * FN;
        int   cur = pwk[0];
        float a   = acc[0];
        #pragma unroll
        for (int k = 1; k < 4; k++) {
            if (pwk[k] == cur) a += acc[k];
            else { atomicAdd(&orow[cur], a); cur = pwk[k]; a = acc[k]; }
        }
        atomicAdd(&orow[cur], a);
    }
    __syncthreads();

    for (int i = tid; i < CPGO * FN; i += T3) {
        const int lc = i >> 4, pw = i & 15;
        out[((size_t)(b * DIM + cbase + lc) * FN + ph) * FN + pw] = out_s[i];
    }
}

extern "C" void kernel_launch(void* const* d_in, const int* in_sizes, int n_in,
                              void* d_out, int out_size)
{
    const float* hr   = (const float*)d_in[0];   // (8,384,112,112)
    // d_in[1] = guidance (unused)
    const float* du   = (const float*)d_in[2];   // (8,16,16,1)
    const float* aw   = (const float*)d_in[3];   // (384,)
    const float* ab   = (const float*)d_in[4];   // (1,)
    const float* wmat = (const float*)d_in[5];   // (7,7)
    const float* bmat = (const float*)d_in[6];   // (7,7)
    float* out = (float*)d_out;                  // (8,384,16,16)

    k1_dot_softmax<<<NSLAB * 2, 392>>>(hr, du, aw, ab, wmat, bmat);
    k3_epilogue<<<NSLAB * NCG2, T3>>>(hr, out);
}

// round 8
// speedup vs baseline: 1.3131x; 1.3131x over previous
#include <cuda_runtime.h>
#include <cstdint>

// AttentionDownsampler v8: v7 structure, but K3 gets a real register budget.
// v5/v6/v7's K3 was pinned at ~43us by __launch_bounds__(448,4) -> 32 regs,
// spilling the 28-float coef array to local memory. launch_bounds(448,2)
// gives ~72 regs: coef + float4 staging stay in registers.

#define DIM     384
#define KS      7
#define NP      49
#define HW      112
#define PLANE   (HW * HW)
#define FN      16
#define NSLAB   128               // (b, ph)
#define SLABPIX 784
#define DROP_P  0.2f

#define CPGO    48                // channels per K3 CTA
#define NCG2    8                 // 384 / 48
#define T3      448               // (x4:28, cc:16)

__device__ float g_attn[(size_t)NSLAB * SLABPIX];   // [slab][pw][49]

// ================= K1: pixel dot + softmax (half-slab CTAs) ==============
__global__ void __launch_bounds__(392, 2)
k1_dot_softmax(const float* __restrict__ hr,
               const float* __restrict__ du,
               const float* __restrict__ aw,
               const float* __restrict__ ab,
               const float* __restrict__ wmat,
               const float* __restrict__ bmat)
{
    __shared__ float awsh[DIM];
    __shared__ float pd_s[392];

    const int bid  = blockIdx.x;
    const int xh   = bid & 1;            // x half: columns [xh*56, xh*56+56)
    const int slab = bid >> 1;
    const int ph   = slab & (FN - 1);
    const int b    = slab >> 4;

    const int tid = threadIdx.x;         // tid = dy*56 + xl
    const int dy  = tid / 56;
    const int xl  = tid - dy * 56;

    if (tid < DIM) awsh[tid] = __ldg(aw + tid);
    __syncthreads();

    const float* gp = hr + (size_t)b * DIM * PLANE
                         + (size_t)(ph * KS + dy) * HW + xh * 56 + xl;

    float s0 = 0.f, s1 = 0.f;
    #pragma unroll 8
    for (int c = 0; c < DIM; c += 2) {
        s0 = fmaf(__ldg(gp + (size_t)c * PLANE),       awsh[c],     s0);
        s1 = fmaf(__ldg(gp + (size_t)(c + 1) * PLANE), awsh[c + 1], s1);
    }
    pd_s[tid] = s0 + s1;
    __syncthreads();

    // softmax: warp w (0..7) handles patch pw = xh*8 + w
    const int wid = tid >> 5, lane = tid & 31;
    if (wid < 8) {
        const int pw = xh * 8 + wid;
        const float m   = (__ldg(du + (b * FN + ph) * FN + pw) > DROP_P) ? 1.f : 0.f;
        const float abv = __ldg(ab);
        const int p0 = lane, p1 = lane + 32;
        float v0 = -1e30f, v1 = -1e30f;
        if (p0 < NP) {
            int d = p0 / KS, e = p0 - d * KS;
            v0 = (pd_s[d * 56 + wid * KS + e] + abv) * m * __ldg(wmat + p0) + __ldg(bmat + p0);
        }
        if (p1 < NP) {
            int d = p1 / KS, e = p1 - d * KS;
            v1 = (pd_s[d * 56 + wid * KS + e] + abv) * m * __ldg(wmat + p1) + __ldg(bmat + p1);
        }
        float mx = fmaxf(v0, v1);
        #pragma unroll
        for (int o = 16; o; o >>= 1)
            mx = fmaxf(mx, __shfl_xor_sync(0xffffffffu, mx, o));
        float e0 = (p0 < NP) ? __expf(v0 - mx) : 0.f;
        float e1 = (p1 < NP) ? __expf(v1 - mx) : 0.f;
        float ss = e0 + e1;
        #pragma unroll
        for (int o = 16; o; o >>= 1)
            ss += __shfl_xor_sync(0xffffffffu, ss, o);
        const float inv = 1.f / ss;
        float* dst = g_attn + (size_t)slab * SLABPIX + pw * NP;
        if (p0 < NP) dst[p0] = e0 * inv;
        if (p1 < NP) dst[p1] = e1 * inv;
    }
}

// ================= K3: channel-looped register epilogue ==================
__global__ void __launch_bounds__(T3, 2)      // ~72 regs: NO spills
k3_epilogue(const float* __restrict__ hr, float* __restrict__ out)
{
    __shared__ float attn_s[SLABPIX];
    __shared__ float out_s[CPGO * FN];   // [48ch][16pw] = 3 KB

    const int bid   = blockIdx.x;
    const int slab  = bid / NCG2;
    const int cg    = (NCG2 - 1) - (bid - slab * NCG2);  // high channels first
    const int ph    = slab & (FN - 1);
    const int b     = slab >> 4;
    const int cbase = cg * CPGO;

    const int tid = threadIdx.x;
    const int x4  = tid % 28;            // float4 column
    const int cc  = tid / 28;            // channel phase 0..15

    for (int i = tid; i < SLABPIX; i += T3)
        attn_s[i] = __ldg(g_attn + (size_t)slab * SLABPIX + i);
    for (int i = tid; i < CPGO * FN; i += T3)
        out_s[i] = 0.f;
    __syncthreads();

    // channel-invariant attn coefficients for this thread's 4 x-positions
    int pwk[4];
    float coef[4][KS];
    #pragma unroll
    for (int k = 0; k < 4; k++) {
        const int x  = 4 * x4 + k;
        const int pw = x / KS;
        pwk[k] = pw;
        const int ci = pw * NP + (x - pw * KS);
        #pragma unroll
        for (int d = 0; d < KS; d++)
            coef[k][d] = attn_s[ci + d * KS];
    }

    const float* base = hr + (size_t)(b * DIM + cbase + cc) * PLANE
                           + (size_t)(ph * KS) * HW;

    #pragma unroll
    for (int g = 0; g < 3; g++) {
        const float4* gp = (const float4*)(base + (size_t)(g * 16) * PLANE) + x4;
        // stage all 7 rows first: 7 independent LDG.128 in flight
        float4 v[KS];
        #pragma unroll
        for (int d = 0; d < KS; d++)
            v[d] = __ldg(gp + d * 28);

        float acc[4] = {0.f, 0.f, 0.f, 0.f};
        #pragma unroll
        for (int d = 0; d < KS; d++) {
            acc[0] = fmaf(v[d].x, coef[0][d], acc[0]);
            acc[1] = fmaf(v[d].y, coef[1][d], acc[1]);
            acc[2] = fmaf(v[d].z, coef[2][d], acc[2]);
            acc[3] = fmaf(v[d].w, coef[3][d], acc[3]);
        }
        // combine the <=2 distinct pw groups into smem
        float* orow = out_s + (g * 16 + cc) * FN;
        int   cur = pwk[0];
        float a   = acc[0];
        #pragma unroll
        for (int k = 1; k < 4; k++) {
            if (pwk[k] == cur) a += acc[k];
            else { atomicAdd(&orow[cur], a); cur = pwk[k]; a = acc[k]; }
        }
        atomicAdd(&orow[cur], a);
    }
    __syncthreads();

    for (int i = tid; i < CPGO * FN; i += T3) {
        const int lc = i >> 4, pw = i & 15;
        out[((size_t)(b * DIM + cbase + lc) * FN + ph) * FN + pw] = out_s[i];
    }
}

extern "C" void kernel_launch(void* const* d_in, const int* in_sizes, int n_in,
                              void* d_out, int out_size)
{
    const float* hr   = (const float*)d_in[0];   // (8,384,112,112)
    // d_in[1] = guidance (unused)
    const float* du   = (const float*)d_in[2];   // (8,16,16,1)
    const float* aw   = (const float*)d_in[3];   // (384,)
    const float* ab   = (const float*)d_in[4];   // (1,)
    const float* wmat = (const float*)d_in[5];   // (7,7)
    const float* bmat = (const float*)d_in[6];   // (7,7)
    float* out = (float*)d_out;                  // (8,384,16,16)

    k1_dot_softmax<<<NSLAB * 2, 392>>>(hr, du, aw, ab, wmat, bmat);
    k3_epilogue<<<NSLAB * NCG2, T3>>>(hr, out);
}

// round 9
// speedup vs baseline: 1.5400x; 1.1728x over previous
#include <cuda_runtime.h>
#include <cstdint>

// AttentionDownsampler v9:
//  K1 (vectorized): CTA=(slab, x-half). thread=(channel-quarter, float4-pos);
//      96 LDG.128/thread, broadcast-LDS aw, 4-way smem-atomic pixel combine,
//      softmax -> g_attnT in PIXEL-TRANSPOSED layout [slab][dy*112 + x].
//  K3: coefs are 7 aligned LDG.128 from g_attnT (L2-hot), issued alongside
//      the hr float4 loads: no attn smem, no prologue barrier. CPGO=32,
//      grid 1536 for small wave-quantization tail.

#define DIM     384
#define KS      7
#define NP      49
#define HW      112
#define PLANE   (HW * HW)
#define PLANE4  (PLANE / 4)
#define FN      16
#define NSLAB   128               // (b, ph)
#define SLABPIX 784
#define DROP_P  0.2f

#define CPGO    32                // channels per K3 CTA
#define NCG2    12                // 384 / 32
#define T3      448               // (x4:28, cc:16)

__device__ float g_attnT[(size_t)NSLAB * SLABPIX];  // [slab][dy*112 + x]

// ================= K1: pixel dot + softmax (vectorized) ==================
__global__ void __launch_bounds__(392, 2)
k1_dot_softmax(const float* __restrict__ hr,
               const float* __restrict__ du,
               const float* __restrict__ aw,
               const float* __restrict__ ab,
               const float* __restrict__ wmat,
               const float* __restrict__ bmat)
{
    __shared__ float awsh[DIM];
    __shared__ float pd_s[392];          // pixel dot for 7 dy x 56 xl

    const int bid  = blockIdx.x;
    const int xh   = bid & 1;            // x half: columns [xh*56, xh*56+56)
    const int slab = bid >> 1;
    const int ph   = slab & (FN - 1);
    const int b    = slab >> 4;

    const int tid = threadIdx.x;         // tid = qr*98 + pos
    const int qr  = tid / 98;            // channel quarter 0..3
    const int pos = tid - qr * 98;       // (dy, x4l): pos = dy*14 + x4l
    const int dy  = pos / 14;
    const int x4l = pos - dy * 14;

    if (tid < DIM) awsh[tid] = __ldg(aw + tid);
    pd_s[tid] = 0.f;
    __syncthreads();

    // float4 pointer for channel c = qr*96, this pixel row, this x-half
    const float4* gp = (const float4*)(hr
        + (size_t)(b * DIM + qr * 96) * PLANE
        + (size_t)(ph * KS + dy) * HW) + (xh * 14 + x4l);

    const float* ap = awsh + qr * 96;
    float4 acc = make_float4(0.f, 0.f, 0.f, 0.f);
    #pragma unroll 8
    for (int t = 0; t < 96; t++) {
        float4 v = __ldg(gp + (size_t)t * PLANE4);
        const float a = ap[t];           // broadcast LDS
        acc.x = fmaf(v.x, a, acc.x);
        acc.y = fmaf(v.y, a, acc.y);
        acc.z = fmaf(v.z, a, acc.z);
        acc.w = fmaf(v.w, a, acc.w);
    }
    {
        float* pc = pd_s + dy * 56 + x4l * 4;    // 4 contributors per cell
        atomicAdd(pc + 0, acc.x);
        atomicAdd(pc + 1, acc.y);
        atomicAdd(pc + 2, acc.z);
        atomicAdd(pc + 3, acc.w);
    }
    __syncthreads();

    // softmax: warp w (0..7) handles patch pw = xh*8 + w; write TRANSPOSED
    const int wid = tid >> 5, lane = tid & 31;
    if (wid < 8) {
        const int pw = xh * 8 + wid;
        const float m   = (__ldg(du + (b * FN + ph) * FN + pw) > DROP_P) ? 1.f : 0.f;
        const float abv = __ldg(ab);
        const int p0 = lane, p1 = lane + 32;
        float v0 = -1e30f, v1 = -1e30f;
        if (p0 < NP) {
            int d = p0 / KS, e = p0 - d * KS;
            v0 = (pd_s[d * 56 + wid * KS + e] + abv) * m * __ldg(wmat + p0) + __ldg(bmat + p0);
        }
        if (p1 < NP) {
            int d = p1 / KS, e = p1 - d * KS;
            v1 = (pd_s[d * 56 + wid * KS + e] + abv) * m * __ldg(wmat + p1) + __ldg(bmat + p1);
        }
        float mx = fmaxf(v0, v1);
        #pragma unroll
        for (int o = 16; o; o >>= 1)
            mx = fmaxf(mx, __shfl_xor_sync(0xffffffffu, mx, o));
        float e0 = (p0 < NP) ? __expf(v0 - mx) : 0.f;
        float e1 = (p1 < NP) ? __expf(v1 - mx) : 0.f;
        float ss = e0 + e1;
        #pragma unroll
        for (int o = 16; o; o >>= 1)
            ss += __shfl_xor_sync(0xffffffffu, ss, o);
        const float inv = 1.f / ss;
        float* dstT = g_attnT + (size_t)slab * SLABPIX;
        if (p0 < NP) {
            int d = p0 / KS, e = p0 - d * KS;
            dstT[d * HW + pw * KS + e] = e0 * inv;
        }
        if (p1 < NP) {
            int d = p1 / KS, e = p1 - d * KS;
            dstT[d * HW + pw * KS + e] = e1 * inv;
        }
    }
}

// ================= K3: register epilogue, transposed coefs ===============
__global__ void __launch_bounds__(T3, 2)
k3_epilogue(const float* __restrict__ hr, float* __restrict__ out)
{
    __shared__ float out_s[CPGO * FN];   // [32ch][16pw] = 2 KB

    const int bid   = blockIdx.x;
    const int slab  = bid / NCG2;
    const int cg    = (NCG2 - 1) - (bid - slab * NCG2);  // high channels first
    const int ph    = slab & (FN - 1);
    const int b     = slab >> 4;
    const int cbase = cg * CPGO;

    const int tid = threadIdx.x;
    const int x4  = tid % 28;            // float4 column
    const int cc  = tid / 28;            // channel phase 0..15

    for (int i = tid; i < CPGO * FN; i += T3) out_s[i] = 0.f;

    // 7 aligned float4 coefficient loads (L2-hot, shared by 12 CTAs)
    const float4* cp = (const float4*)(g_attnT + (size_t)slab * SLABPIX) + x4;
    float4 coef[KS];
    #pragma unroll
    for (int d = 0; d < KS; d++)
        coef[d] = __ldg(cp + d * 28);

    // pw mapping for this thread's 4 x positions
    int pwk[4];
    #pragma unroll
    for (int k = 0; k < 4; k++) pwk[k] = (4 * x4 + k) / KS;

    const float* base = hr + (size_t)(b * DIM + cbase + cc) * PLANE
                           + (size_t)(ph * KS) * HW;
    __syncthreads();                      // out_s zeroed

    #pragma unroll
    for (int g = 0; g < 2; g++) {
        const float4* gp = (const float4*)(base + (size_t)(g * 16) * PLANE) + x4;
        float4 v[KS];
        #pragma unroll
        for (int d = 0; d < KS; d++)
            v[d] = __ldg(gp + d * 28);

        float acc[4] = {0.f, 0.f, 0.f, 0.f};
        #pragma unroll
        for (int d = 0; d < KS; d++) {
            acc[0] = fmaf(v[d].x, coef[d].x, acc[0]);
            acc[1] = fmaf(v[d].y, coef[d].y, acc[1]);
            acc[2] = fmaf(v[d].z, coef[d].z, acc[2]);
            acc[3] = fmaf(v[d].w, coef[d].w, acc[3]);
        }
        float* orow = out_s + (g * 16 + cc) * FN;
        int   cur = pwk[0];
        float a   = acc[0];
        #pragma unroll
        for (int k = 1; k < 4; k++) {
            if (pwk[k] == cur) a += acc[k];
            else { atomicAdd(&orow[cur], a); cur = pwk[k]; a = acc[k]; }
        }
        atomicAdd(&orow[cur], a);
    }
    __syncthreads();

    for (int i = tid; i < CPGO * FN; i += T3) {
        const int lc = i >> 4, pw = i & 15;
        out[((size_t)(b * DIM + cbase + lc) * FN + ph) * FN + pw] = out_s[i];
    }
}

extern "C" void kernel_launch(void* const* d_in, const int* in_sizes, int n_in,
                              void* d_out, int out_size)
{
    const float* hr   = (const float*)d_in[0];   // (8,384,112,112)
    // d_in[1] = guidance (unused)
    const float* du   = (const float*)d_in[2];   // (8,16,16,1)
    const float* aw   = (const float*)d_in[3];   // (384,)
    const float* ab   = (const float*)d_in[4];   // (1,)
    const float* wmat = (const float*)d_in[5];   // (7,7)
    const float* bmat = (const float*)d_in[6];   // (7,7)
    float* out = (float*)d_out;                  // (8,384,16,16)

    k1_dot_softmax<<<NSLAB * 2, 392>>>(hr, du, aw, ab, wmat, bmat);
    k3_epilogue<<<NSLAB * NCG2, T3>>>(hr, out);
}